// round 8
// baseline (speedup 1.0000x reference)
#include <cuda_runtime.h>
#include <cstdint>
#include <math.h>

// ---------------------------------------------------------------------------
// Problem constants
// ---------------------------------------------------------------------------
#define B_   4
#define S_   2048
#define H_   1024
#define NH_  16
#define HD_  64
#define E_   4096
#define M_   (B_ * S_)          // 8192 tokens
#define QKV_N (3 * H_)          // 3072

// ---------------------------------------------------------------------------
// Scratch (device globals — no allocation allowed)
// ---------------------------------------------------------------------------
__device__ float g_h  [M_ * H_];     // ln1 output (perm+tf32)
__device__ float g_qkv[M_ * QKV_N];  // qkv: Q,K perm+tf32; V plain tf32
__device__ float g_o  [M_ * H_];     // attention output (perm+tf32)
__device__ float g_x2 [M_ * H_];     // x + attn@Wo + bo (plain fp32)
__device__ float g_h2 [M_ * H_];     // ln2 output (perm+tf32)
__device__ float g_a  [M_ * E_];     // gelu(fc1) (perm+tf32)
// transposed+rounded weights: [N][K] with k-permuted 16-blocks
__device__ float g_wqkvT[QKV_N * H_];
__device__ float g_woT  [H_ * H_];
__device__ float g_w1T  [E_ * H_];
__device__ float g_w2T  [H_ * E_];

// ---------------------------------------------------------------------------
// Helpers
// ---------------------------------------------------------------------------
__device__ __forceinline__ uint32_t smem_u32(const void* p) {
    uint32_t a;
    asm("{ .reg .u64 t; cvta.to.shared.u64 t, %1; cvt.u32.u64 %0, t; }"
        : "=r"(a) : "l"(p));
    return a;
}
// tf32 round-to-nearest (rna); result returned as float bits
__device__ __forceinline__ float tf32r(float x) {
    uint32_t r;
    asm("cvt.rna.tf32.f32 %0, %1;" : "=r"(r) : "f"(x));
    return __uint_as_float(r);
}
// position of element k within the k-permuted layout (within 16-blocks)
__device__ __forceinline__ int pj(int k) {
    return (k & ~15) | ((k & 3) << 2) | ((k >> 2) & 3);
}

__device__ __forceinline__ void mma_tf32(float* c, const uint32_t* a, const uint32_t* b) {
    asm volatile(
        "mma.sync.aligned.m16n8k8.row.col.f32.tf32.tf32.f32 "
        "{%0,%1,%2,%3}, {%4,%5,%6,%7}, {%8,%9}, {%0,%1,%2,%3};"
        : "+f"(c[0]), "+f"(c[1]), "+f"(c[2]), "+f"(c[3])
        : "r"(a[0]), "r"(a[1]), "r"(a[2]), "r"(a[3]), "r"(b[0]), "r"(b[1]));
}

#define CP_ASYNC16(saddr, gptr) \
    asm volatile("cp.async.cg.shared.global [%0], [%1], 16;" \
        :: "r"(saddr), "l"(gptr) : "memory")
#define CP_COMMIT() asm volatile("cp.async.commit_group;" ::: "memory")

// ---------------------------------------------------------------------------
// Weight transpose + tf32-round + k-permute:  W[K][N] -> WT[N][K]
// ---------------------------------------------------------------------------
__global__ __launch_bounds__(256) void wtrans(
    const float* __restrict__ W, float* __restrict__ WT, int K, int N)
{
    __shared__ float t[32][33];
    const int n0 = blockIdx.x * 32, k0 = blockIdx.y * 32;
    const int tx = threadIdx.x & 31, ty = threadIdx.x >> 5;
#pragma unroll
    for (int r = 0; r < 4; r++)
        t[ty + 8 * r][tx] = W[(size_t)(k0 + ty + 8 * r) * N + n0 + tx];
    __syncthreads();
#pragma unroll
    for (int r = 0; r < 4; r++) {
        const int n = n0 + ty + 8 * r;
        const int k = k0 + tx;
        WT[(size_t)n * K + pj(k)] = tf32r(t[tx][ty + 8 * r]);
    }
}

// ---------------------------------------------------------------------------
// TF32 tensor-core GEMM v3: C[M,N] = A[M,K] @ B[K,N] + bias (+res/gelu)
// CTA 128x256, BK=32 (two 16-blocks), 256 threads, 8 warps (2m x 4n),
// warp tile 64x64. 3-stage cp.async pipeline (48KB/stage).
// mode 1: bias+residual (plain out); mode 2: bias+GELU (perm+tf32 out);
// mode 3: bias, QKV layout (cols<2048 perm+tf32, else plain tf32)
// ---------------------------------------------------------------------------
#define GBM 128
#define GBN 256
#define A_BLK 8192                       // 128 rows x 16 floats
#define B_BLK 16384                      // 256 rows x 16 floats
#define STAGE_BYTES (2 * A_BLK + 2 * B_BLK)   // 49152
#define GEMM_SMEM   (3 * STAGE_BYTES)         // 147456

__global__ __launch_bounds__(256, 1) void gemm_mma(
    const float* __restrict__ A, const float* __restrict__ BT,
    const float* __restrict__ bias, const float* __restrict__ R,
    float* __restrict__ C, int M, int N, int K, int mode)
{
    extern __shared__ char smem[];
    const int tid = threadIdx.x;
    const int wid = tid >> 5, lane = tid & 31;
    const int gID = lane >> 2, tIG = lane & 3;
    const int warp_m = wid & 1, warp_n = wid >> 1;   // 2 x 4
    const int brow = blockIdx.y * GBM, bcol = blockIdx.x * GBN;
    const uint32_t sb = smem_u32(smem);

    // loader: row = tid>>3 (0..31), chunk = tid&7 (16B each, k-contiguous)
    const int lrow = tid >> 3;
    const int lch  = tid & 7;
    const float* Ag = A  + (size_t)(brow + lrow) * K + lch * 4;
    const float* Bg = BT + (size_t)(bcol + lrow) * K + lch * 4;
    const uint32_t aoff = (uint32_t)((lch >> 2) * A_BLK + lrow * 64 + (lch & 3) * 16);
    const uint32_t boff = (uint32_t)(2 * A_BLK + (lch >> 2) * B_BLK + lrow * 64 + (lch & 3) * 16);

    float acc[4][8][4];
#pragma unroll
    for (int i = 0; i < 4; i++)
#pragma unroll
        for (int j = 0; j < 8; j++)
#pragma unroll
            for (int t = 0; t < 4; t++) acc[i][j][t] = 0.f;

    const int nt_tiles = K >> 5;

    auto issue = [&](int kt) {
        const uint32_t st = sb + (uint32_t)(kt % 3) * STAGE_BYTES;
        const float* ga = Ag + kt * 32;
        const float* gb = Bg + kt * 32;
#pragma unroll
        for (int p = 0; p < 4; p++)
            CP_ASYNC16(st + aoff + p * 32 * 64, ga + (size_t)(p * 32) * K);
#pragma unroll
        for (int p = 0; p < 8; p++)
            CP_ASYNC16(st + boff + p * 32 * 64, gb + (size_t)(p * 32) * K);
        CP_COMMIT();
    };

    issue(0); issue(1); issue(2);

    const int m_base = warp_m * 64;
    const int n_base = warp_n * 64;

    for (int kt = 0; kt < nt_tiles; kt++) {
        if (kt + 1 < nt_tiles) {
            if (kt == 0) asm volatile("cp.async.wait_group 2;" ::: "memory");
            else         asm volatile("cp.async.wait_group 1;" ::: "memory");
        } else {
            asm volatile("cp.async.wait_group 0;" ::: "memory");
        }
        __syncthreads();
        // safe now: all warps finished reading stage (kt-1)%3 == (kt+2)%3
        if (kt >= 1 && kt + 2 < nt_tiles) issue(kt + 2);

        const char* stage = smem + (size_t)(kt % 3) * STAGE_BYTES;
#pragma unroll
        for (int kb = 0; kb < 2; kb++) {
            const uint32_t* as = (const uint32_t*)(stage + kb * A_BLK);
            const uint32_t* bs = (const uint32_t*)(stage + 2 * A_BLK + kb * B_BLK);

            uint4 av0[4], av1[4], bv[8];
#pragma unroll
            for (int mt = 0; mt < 4; mt++) {
                const uint32_t* p = as + (m_base + mt * 16 + gID) * 16 + tIG * 4;
                av0[mt] = *(const uint4*)p;
                av1[mt] = *(const uint4*)(p + 128);
            }
#pragma unroll
            for (int nt = 0; nt < 8; nt++)
                bv[nt] = *(const uint4*)(bs + (n_base + nt * 8 + gID) * 16 + tIG * 4);

#pragma unroll
            for (int mt = 0; mt < 4; mt++) {
                const uint32_t aa0[4] = {av0[mt].x, av1[mt].x, av0[mt].y, av1[mt].y};
                const uint32_t aa1[4] = {av0[mt].z, av1[mt].z, av0[mt].w, av1[mt].w};
#pragma unroll
                for (int nt = 0; nt < 8; nt++) {
                    const uint32_t bb0[2] = {bv[nt].x, bv[nt].y};
                    const uint32_t bb1[2] = {bv[nt].z, bv[nt].w};
                    mma_tf32(acc[mt][nt], aa0, bb0);
                    mma_tf32(acc[mt][nt], aa1, bb1);
                }
            }
        }
    }

    // --- epilogue ---
#pragma unroll
    for (int mt = 0; mt < 4; mt++) {
#pragma unroll
        for (int half = 0; half < 2; half++) {
            const int row = brow + m_base + mt * 16 + gID + half * 8;
            float* crow = C + (size_t)row * N;
            const float* rrow = (mode == 1) ? (R + (size_t)row * N) : nullptr;
#pragma unroll
            for (int nt = 0; nt < 8; nt++) {
                const int col = bcol + n_base + nt * 8 + tIG * 2;
                float v0 = acc[mt][nt][half * 2 + 0];
                float v1 = acc[mt][nt][half * 2 + 1];
                const float2 bb = *(const float2*)(bias + col);
                v0 += bb.x; v1 += bb.y;
                if (mode == 1) {
                    const float2 rr = *(const float2*)(rrow + col);
                    v0 += rr.x; v1 += rr.y;
                    *(float2*)(crow + col) = make_float2(v0, v1);
                } else if (mode == 2) {
                    v0 = 0.5f * v0 * (1.f + erff(v0 * 0.70710678118654752f));
                    v1 = 0.5f * v1 * (1.f + erff(v1 * 0.70710678118654752f));
                    crow[pj(col)]     = tf32r(v0);
                    crow[pj(col + 1)] = tf32r(v1);
                } else { // mode 3: QKV layout
                    if (col < 2 * H_) {
                        crow[pj(col)]     = tf32r(v0);
                        crow[pj(col + 1)] = tf32r(v1);
                    } else {
                        crow[col]     = tf32r(v0);
                        crow[col + 1] = tf32r(v1);
                    }
                }
            }
        }
    }
}

// ---------------------------------------------------------------------------
// LayerNorm: one block per row of 1024; output tf32-rounded + k-permuted
// ---------------------------------------------------------------------------
__global__ __launch_bounds__(256) void ln_kernel(
    const float* __restrict__ x, const float* __restrict__ w,
    const float* __restrict__ b, float* __restrict__ out)
{
    const int row = blockIdx.x;
    const int tid = threadIdx.x;
    const float* xr = x + (size_t)row * H_;

    float v[4];
    float s = 0.f, s2 = 0.f;
#pragma unroll
    for (int i = 0; i < 4; i++) {
        v[i] = xr[tid + 256 * i];
        s += v[i];
        s2 += v[i] * v[i];
    }
#pragma unroll
    for (int off = 16; off > 0; off >>= 1) {
        s  += __shfl_xor_sync(0xffffffffu, s,  off);
        s2 += __shfl_xor_sync(0xffffffffu, s2, off);
    }
    __shared__ float red[8], red2[8];
    const int wid = tid >> 5, lane = tid & 31;
    if (lane == 0) { red[wid] = s; red2[wid] = s2; }
    __syncthreads();
    if (tid < 32) {
        float a = (tid < 8) ? red[tid]  : 0.f;
        float c = (tid < 8) ? red2[tid] : 0.f;
#pragma unroll
        for (int off = 4; off > 0; off >>= 1) {
            a += __shfl_xor_sync(0xffffffffu, a, off);
            c += __shfl_xor_sync(0xffffffffu, c, off);
        }
        if (tid == 0) { red[0] = a; red2[0] = c; }
    }
    __syncthreads();
    const float mu  = red[0] * (1.f / H_);
    const float var = red2[0] * (1.f / H_) - mu * mu;
    const float rstd = rsqrtf(var + 1e-5f);

    float* orow = out + (size_t)row * H_;
#pragma unroll
    for (int i = 0; i < 4; i++) {
        const int c = tid + 256 * i;
        orow[pj(c)] = tf32r((v[i] - mu) * rstd * w[c] + b[c]);
    }
}

// ---------------------------------------------------------------------------
// Tensor-core flash attention (unchanged from round 7).
// ---------------------------------------------------------------------------
#define QSTR 80
#define PSTR 68
#define ATTN_SMEM ((3 * 64 * QSTR + 64 * PSTR) * 4)

__global__ __launch_bounds__(128) void attn_mma(
    const float* __restrict__ qkv, float* __restrict__ O)
{
    extern __shared__ float sm[];
    float* Qs = sm;                    // [64][QSTR] (d permuted)
    float* Ks = Qs + 64 * QSTR;        // [64][QSTR] (d permuted)
    float* VT = Ks + 64 * QSTR;        // [d=64][QSTR] (kv permuted)
    float* Ps = VT + 64 * QSTR;        // [q=64][PSTR] (kv permuted)

    const int qt = blockIdx.x, bh = blockIdx.y;
    const int b = bh >> 4, h = bh & 15;
    const int tid = threadIdx.x, wid = tid >> 5, lane = tid & 31;
    const int gID = lane >> 2, tIG = lane & 3;
    const size_t row_base = (size_t)b * S_;
    const int qoff = h * HD_, koff = H_ + h * HD_, voff = 2 * H_ + h * HD_;

    // --- load Q tile (straight copy; already perm+tf32) ---
    {
        const int r = tid >> 1, ch = (tid & 1) * 32;
        const float4* src = (const float4*)(qkv + (row_base + qt * 64 + r) * QKV_N + qoff + ch);
        float4* dst = (float4*)(Qs + r * QSTR + ch);
#pragma unroll
        for (int j = 0; j < 8; j++) dst[j] = src[j];
    }
    __syncthreads();

    uint4 qa[4], qb[4];
    const int qrow = wid * 16 + gID;
#pragma unroll
    for (int kb = 0; kb < 4; kb++) {
        qa[kb] = *(const uint4*)(Qs + qrow * QSTR + kb * 16 + tIG * 4);
        qb[kb] = *(const uint4*)(Qs + (qrow + 8) * QSTR + kb * 16 + tIG * 4);
    }

    float m0 = -1e30f, m1 = -1e30f, l0 = 0.f, l1 = 0.f;
    float oacc[8][4];
#pragma unroll
    for (int i = 0; i < 8; i++)
#pragma unroll
        for (int j = 0; j < 4; j++) oacc[i][j] = 0.f;

    const float scale = 0.125f;

    for (int kt = 0; kt < S_ / 64; kt++) {
        __syncthreads();

        {
            const int r = tid >> 1, ch = (tid & 1) * 32;
            const float* gk = qkv + (row_base + kt * 64 + r) * QKV_N + koff + ch;
            const uint32_t sk = smem_u32(Ks + r * QSTR + ch);
#pragma unroll
            for (int j = 0; j < 8; j++) CP_ASYNC16(sk + j * 16, gk + j * 4);
            CP_COMMIT();
        }
        {
            const int kv = tid & 63, half = tid >> 6;
            const float4* gv = (const float4*)(qkv + (row_base + kt * 64 + kv) * QKV_N + voff + half * 32);
            const int pk = pj(kv);
#pragma unroll
            for (int j = 0; j < 8; j++) {
                const float4 v = gv[j];
                const int d = half * 32 + j * 4;
                VT[(d + 0) * QSTR + pk] = v.x;
                VT[(d + 1) * QSTR + pk] = v.y;
                VT[(d + 2) * QSTR + pk] = v.z;
                VT[(d + 3) * QSTR + pk] = v.w;
            }
        }
        asm volatile("cp.async.wait_group 0;" ::: "memory");
        __syncthreads();

        float sacc[8][4];
#pragma unroll
        for (int i = 0; i < 8; i++)
#pragma unroll
            for (int j = 0; j < 4; j++) sacc[i][j] = 0.f;

#pragma unroll
        for (int kb = 0; kb < 4; kb++) {
            const uint32_t aa0[4] = {qa[kb].x, qb[kb].x, qa[kb].y, qb[kb].y};
            const uint32_t aa1[4] = {qa[kb].z, qb[kb].z, qa[kb].w, qb[kb].w};
#pragma unroll
            for (int nt = 0; nt < 8; nt++) {
                const uint4 kv8 = *(const uint4*)(Ks + (nt * 8 + gID) * QSTR + kb * 16 + tIG * 4);
                const uint32_t bb0[2] = {kv8.x, kv8.y};
                const uint32_t bb1[2] = {kv8.z, kv8.w};
                mma_tf32(sacc[nt], aa0, bb0);
                mma_tf32(sacc[nt], aa1, bb1);
            }
        }

        float mx0 = -1e30f, mx1 = -1e30f;
#pragma unroll
        for (int nt = 0; nt < 8; nt++) {
            mx0 = fmaxf(mx0, fmaxf(sacc[nt][0], sacc[nt][1]));
            mx1 = fmaxf(mx1, fmaxf(sacc[nt][2], sacc[nt][3]));
        }
        mx0 = fmaxf(mx0, __shfl_xor_sync(0xffffffffu, mx0, 1));
        mx0 = fmaxf(mx0, __shfl_xor_sync(0xffffffffu, mx0, 2));
        mx1 = fmaxf(mx1, __shfl_xor_sync(0xffffffffu, mx1, 1));
        mx1 = fmaxf(mx1, __shfl_xor_sync(0xffffffffu, mx1, 2));

        const float mn0 = fmaxf(m0, mx0 * scale);
        const float mn1 = fmaxf(m1, mx1 * scale);
        const float corr0 = __expf(m0 - mn0);
        const float corr1 = __expf(m1 - mn1);

        float sum0 = 0.f, sum1 = 0.f;
#pragma unroll
        for (int nt = 0; nt < 8; nt++) {
            float p0 = tf32r(__expf(sacc[nt][0] * scale - mn0));
            float p1 = tf32r(__expf(sacc[nt][1] * scale - mn0));
            float p2 = tf32r(__expf(sacc[nt][2] * scale - mn1));
            float p3 = tf32r(__expf(sacc[nt][3] * scale - mn1));
            sum0 += p0 + p1; sum1 += p2 + p3;
            sacc[nt][0] = p0; sacc[nt][1] = p1; sacc[nt][2] = p2; sacc[nt][3] = p3;
        }
        sum0 += __shfl_xor_sync(0xffffffffu, sum0, 1);
        sum0 += __shfl_xor_sync(0xffffffffu, sum0, 2);
        sum1 += __shfl_xor_sync(0xffffffffu, sum1, 1);
        sum1 += __shfl_xor_sync(0xffffffffu, sum1, 2);

        l0 = l0 * corr0 + sum0; m0 = mn0;
        l1 = l1 * corr1 + sum1; m1 = mn1;
#pragma unroll
        for (int nt = 0; nt < 8; nt++) {
            oacc[nt][0] *= corr0; oacc[nt][1] *= corr0;
            oacc[nt][2] *= corr1; oacc[nt][3] *= corr1;
        }

#pragma unroll
        for (int nt = 0; nt < 8; nt++) {
            const int c = nt * 8 + tIG * 2;
            const int pc0 = pj(c), pc1 = pj(c + 1);
            Ps[qrow * PSTR + pc0]       = sacc[nt][0];
            Ps[qrow * PSTR + pc1]       = sacc[nt][1];
            Ps[(qrow + 8) * PSTR + pc0] = sacc[nt][2];
            Ps[(qrow + 8) * PSTR + pc1] = sacc[nt][3];
        }
        __syncwarp();

#pragma unroll
        for (int kb = 0; kb < 4; kb++) {
            const uint4 pa = *(const uint4*)(Ps + qrow * PSTR + kb * 16 + tIG * 4);
            const uint4 pb = *(const uint4*)(Ps + (qrow + 8) * PSTR + kb * 16 + tIG * 4);
            const uint32_t aa0[4] = {pa.x, pb.x, pa.y, pb.y};
            const uint32_t aa1[4] = {pa.z, pb.z, pa.w, pb.w};
#pragma unroll
            for (int nt = 0; nt < 8; nt++) {
                const uint4 vv = *(const uint4*)(VT + (nt * 8 + gID) * QSTR + kb * 16 + tIG * 4);
                const uint32_t bb0[2] = {vv.x, vv.y};
                const uint32_t bb1[2] = {vv.z, vv.w};
                mma_tf32(oacc[nt], aa0, bb0);
                mma_tf32(oacc[nt], aa1, bb1);
            }
        }
    }

    const float il0 = 1.f / l0, il1 = 1.f / l1;
    float* orow0 = O + (row_base + qt * 64 + qrow) * H_;
    float* orow1 = O + (row_base + qt * 64 + qrow + 8) * H_;
#pragma unroll
    for (int nt = 0; nt < 8; nt++) {
        const int c = h * HD_ + nt * 8 + tIG * 2;
        const int pc0 = pj(c), pc1 = pj(c + 1);
        orow0[pc0] = tf32r(oacc[nt][0] * il0);
        orow0[pc1] = tf32r(oacc[nt][1] * il0);
        orow1[pc0] = tf32r(oacc[nt][2] * il1);
        orow1[pc1] = tf32r(oacc[nt][3] * il1);
    }
}

// ---------------------------------------------------------------------------
// Launch
// ---------------------------------------------------------------------------
extern "C" void kernel_launch(void* const* d_in, const int* in_sizes, int n_in,
                              void* d_out, int out_size)
{
    const float* x     = (const float*)d_in[0];
    const float* ln1_w = (const float*)d_in[1];
    const float* ln1_b = (const float*)d_in[2];
    const float* Wqkv  = (const float*)d_in[3];
    const float* bqkv  = (const float*)d_in[4];
    const float* Wo    = (const float*)d_in[5];
    const float* bo    = (const float*)d_in[6];
    const float* ln2_w = (const float*)d_in[7];
    const float* ln2_b = (const float*)d_in[8];
    const float* fc1_w = (const float*)d_in[9];
    const float* fc1_b = (const float*)d_in[10];
    const float* fc2_w = (const float*)d_in[11];
    const float* fc2_b = (const float*)d_in[12];
    float* out = (float*)d_out;

    float *h, *qkv, *o, *x2, *h2, *a, *wqkvT, *woT, *w1T, *w2T;
    cudaGetSymbolAddress((void**)&h,   g_h);
    cudaGetSymbolAddress((void**)&qkv, g_qkv);
    cudaGetSymbolAddress((void**)&o,   g_o);
    cudaGetSymbolAddress((void**)&x2,  g_x2);
    cudaGetSymbolAddress((void**)&h2,  g_h2);
    cudaGetSymbolAddress((void**)&a,   g_a);
    cudaGetSymbolAddress((void**)&wqkvT, g_wqkvT);
    cudaGetSymbolAddress((void**)&woT,   g_woT);
    cudaGetSymbolAddress((void**)&w1T,   g_w1T);
    cudaGetSymbolAddress((void**)&w2T,   g_w2T);

    cudaFuncSetAttribute(attn_mma,
                         cudaFuncAttributeMaxDynamicSharedMemorySize, ATTN_SMEM);
    cudaFuncSetAttribute(gemm_mma,
                         cudaFuncAttributeMaxDynamicSharedMemorySize, GEMM_SMEM);

    // 0) weight prepass: transpose + tf32-round + k-permute
    wtrans<<<dim3(QKV_N / 32, H_ / 32), 256>>>(Wqkv, wqkvT, H_, QKV_N);
    wtrans<<<dim3(H_ / 32,    H_ / 32), 256>>>(Wo,   woT,   H_, H_);
    wtrans<<<dim3(E_ / 32,    H_ / 32), 256>>>(fc1_w, w1T,  H_, E_);
    wtrans<<<dim3(H_ / 32,    E_ / 32), 256>>>(fc2_w, w2T,  E_, H_);

    // 1) LN1 (perm+tf32 out)
    ln_kernel<<<M_, 256>>>(x, ln1_w, ln1_b, h);
    // 2) QKV projection (mode 3: Q,K perm+tf32; V plain tf32)
    gemm_mma<<<dim3(QKV_N / GBN, M_ / GBM), 256, GEMM_SMEM>>>(
        h, wqkvT, bqkv, nullptr, qkv, M_, QKV_N, H_, 3);
    // 3) attention (tensor cores; perm+tf32 out)
    attn_mma<<<dim3(S_ / 64, B_ * NH_), 128, ATTN_SMEM>>>(qkv, o);
    // 4) Wo + residual
    gemm_mma<<<dim3(H_ / GBN, M_ / GBM), 256, GEMM_SMEM>>>(
        o, woT, bo, x, x2, M_, H_, H_, 1);
    // 5) LN2 (perm+tf32 out)
    ln_kernel<<<M_, 256>>>(x2, ln2_w, ln2_b, h2);
    // 6) FC1 + GELU (perm+tf32 out)
    gemm_mma<<<dim3(E_ / GBN, M_ / GBM), 256, GEMM_SMEM>>>(
        h2, w1T, fc1_b, nullptr, a, M_, E_, H_, 2);
    // 7) FC2 + residual -> out
    gemm_mma<<<dim3(H_ / GBN, M_ / GBM), 256, GEMM_SMEM>>>(
        a, w2T, fc2_b, x2, out, M_, H_, E_, 1);
}

// round 9
// speedup vs baseline: 1.0565x; 1.0565x over previous
#include <cuda_runtime.h>
#include <cstdint>
#include <math.h>

// ---------------------------------------------------------------------------
// Problem constants
// ---------------------------------------------------------------------------
#define B_   4
#define S_   2048
#define H_   1024
#define NH_  16
#define HD_  64
#define E_   4096
#define M_   (B_ * S_)          // 8192 tokens
#define QKV_N (3 * H_)          // 3072

// ---------------------------------------------------------------------------
// Scratch (device globals — no allocation allowed)
// ---------------------------------------------------------------------------
__device__ float g_h  [M_ * H_];     // ln1 output (perm+tf32)
__device__ float g_qkv[M_ * QKV_N];  // qkv: Q,K perm+tf32; V plain tf32
__device__ float g_o  [M_ * H_];     // attention output (perm+tf32)
__device__ float g_x2 [M_ * H_];     // x + attn@Wo + bo (plain fp32)
__device__ float g_h2 [M_ * H_];     // ln2 output (perm+tf32)
__device__ float g_a  [M_ * E_];     // gelu(fc1) (perm+tf32)
// transposed+rounded weights: [N][K] with k-permuted 16-blocks
__device__ float g_wqkvT[QKV_N * H_];
__device__ float g_woT  [H_ * H_];
__device__ float g_w1T  [E_ * H_];
__device__ float g_w2T  [H_ * E_];

// ---------------------------------------------------------------------------
// Helpers
// ---------------------------------------------------------------------------
__device__ __forceinline__ uint32_t smem_u32(const void* p) {
    uint32_t a;
    asm("{ .reg .u64 t; cvta.to.shared.u64 t, %1; cvt.u32.u64 %0, t; }"
        : "=r"(a) : "l"(p));
    return a;
}
// tf32 round-to-nearest (rna); result returned as float bits
__device__ __forceinline__ float tf32r(float x) {
    uint32_t r;
    asm("cvt.rna.tf32.f32 %0, %1;" : "=r"(r) : "f"(x));
    return __uint_as_float(r);
}
// position of element k within the k-permuted layout (within 16-blocks)
__device__ __forceinline__ int pj(int k) {
    return (k & ~15) | ((k & 3) << 2) | ((k >> 2) & 3);
}

__device__ __forceinline__ void mma_tf32(float* c, const uint32_t* a, const uint32_t* b) {
    asm volatile(
        "mma.sync.aligned.m16n8k8.row.col.f32.tf32.tf32.f32 "
        "{%0,%1,%2,%3}, {%4,%5,%6,%7}, {%8,%9}, {%0,%1,%2,%3};"
        : "+f"(c[0]), "+f"(c[1]), "+f"(c[2]), "+f"(c[3])
        : "r"(a[0]), "r"(a[1]), "r"(a[2]), "r"(a[3]), "r"(b[0]), "r"(b[1]));
}

#define CP_ASYNC16(saddr, gptr) \
    asm volatile("cp.async.cg.shared.global [%0], [%1], 16;" \
        :: "r"(saddr), "l"(gptr) : "memory")
#define CP_COMMIT() asm volatile("cp.async.commit_group;" ::: "memory")

// ---------------------------------------------------------------------------
// Weight transpose + tf32-round + k-permute:  W[K][N] -> WT[N][K]
// ---------------------------------------------------------------------------
__global__ __launch_bounds__(256) void wtrans(
    const float* __restrict__ W, float* __restrict__ WT, int K, int N)
{
    __shared__ float t[32][33];
    const int n0 = blockIdx.x * 32, k0 = blockIdx.y * 32;
    const int tx = threadIdx.x & 31, ty = threadIdx.x >> 5;
#pragma unroll
    for (int r = 0; r < 4; r++)
        t[ty + 8 * r][tx] = W[(size_t)(k0 + ty + 8 * r) * N + n0 + tx];
    __syncthreads();
#pragma unroll
    for (int r = 0; r < 4; r++) {
        const int n = n0 + ty + 8 * r;
        const int k = k0 + tx;
        WT[(size_t)n * K + pj(k)] = tf32r(t[tx][ty + 8 * r]);
    }
}

// ---------------------------------------------------------------------------
// TF32 tensor-core GEMM v4: 128x128 CTA, BK=32 (two 16-blocks), 256 threads,
// 8 warps (2m x 4n), warp tile 64x32, 3-stage cp.async (32KB/stage),
// 2 CTAs/SM. One __syncthreads per 32-K.
// mode 1: bias+residual (plain out); mode 2: bias+GELU (perm+tf32 out);
// mode 3: bias, QKV layout (cols<2048 perm+tf32, else plain tf32)
// ---------------------------------------------------------------------------
#define A16 8192                         // one 16-block: 128 rows x 16 floats
#define STAGE_BYTES (4 * A16)            // A(2 blocks) + B(2 blocks) = 32KB
#define GEMM_SMEM   (3 * STAGE_BYTES)    // 98304 per CTA

__global__ __launch_bounds__(256, 2) void gemm_mma(
    const float* __restrict__ A, const float* __restrict__ BT,
    const float* __restrict__ bias, const float* __restrict__ R,
    float* __restrict__ C, int M, int N, int K, int mode)
{
    extern __shared__ char smem[];
    const int tid = threadIdx.x;
    const int wid = tid >> 5, lane = tid & 31;
    const int gID = lane >> 2, tIG = lane & 3;
    const int warp_m = wid & 1, warp_n = wid >> 1;   // 2 x 4
    const int brow = blockIdx.y * 128, bcol = blockIdx.x * 128;
    const uint32_t sb = smem_u32(smem);

    // loader: row = tid>>3 (0..31), chunk = tid&7 (16B, k-contiguous 128B row)
    const int lrow = tid >> 3;
    const int lch  = tid & 7;
    const float* Ag = A  + (size_t)(brow + lrow) * K + lch * 4;
    const float* Bg = BT + (size_t)(bcol + lrow) * K + lch * 4;
    const uint32_t aoff = (uint32_t)((lch >> 2) * A16 + lrow * 64 + (lch & 3) * 16);
    const uint32_t boff = aoff + 2 * A16;

    float acc[4][4][4];
#pragma unroll
    for (int i = 0; i < 4; i++)
#pragma unroll
        for (int j = 0; j < 4; j++)
#pragma unroll
            for (int t = 0; t < 4; t++) acc[i][j][t] = 0.f;

    const int nt_tiles = K >> 5;

    auto issue = [&](int kt) {
        const uint32_t st = sb + (uint32_t)(kt % 3) * STAGE_BYTES;
        const float* ga = Ag + kt * 32;
        const float* gb = Bg + kt * 32;
#pragma unroll
        for (int p = 0; p < 4; p++) {
            CP_ASYNC16(st + aoff + p * 2048, ga + (size_t)(p * 32) * K);
            CP_ASYNC16(st + boff + p * 2048, gb + (size_t)(p * 32) * K);
        }
        CP_COMMIT();
    };

    issue(0); issue(1);

    const int m_base = warp_m * 64;
    const int n_base = warp_n * 32;

    for (int kt = 0; kt < nt_tiles; kt++) {
        if (kt + 1 < nt_tiles) asm volatile("cp.async.wait_group 1;" ::: "memory");
        else                   asm volatile("cp.async.wait_group 0;" ::: "memory");
        __syncthreads();
        // all warps done reading buffer (kt+2)%3 (used in iter kt-1) -> refill now
        if (kt + 2 < nt_tiles) issue(kt + 2);

        const char* stage = smem + (size_t)(kt % 3) * STAGE_BYTES;
#pragma unroll
        for (int kb = 0; kb < 2; kb++) {
            const uint32_t* as = (const uint32_t*)(stage + kb * A16);
            const uint32_t* bs = (const uint32_t*)(stage + 2 * A16 + kb * A16);

            uint4 av0[4], av1[4], bv[4];
#pragma unroll
            for (int mt = 0; mt < 4; mt++) {
                const uint32_t* p = as + (m_base + mt * 16 + gID) * 16 + tIG * 4;
                av0[mt] = *(const uint4*)p;
                av1[mt] = *(const uint4*)(p + 128);
            }
#pragma unroll
            for (int nt = 0; nt < 4; nt++)
                bv[nt] = *(const uint4*)(bs + (n_base + nt * 8 + gID) * 16 + tIG * 4);

#pragma unroll
            for (int mt = 0; mt < 4; mt++) {
                const uint32_t aa0[4] = {av0[mt].x, av1[mt].x, av0[mt].y, av1[mt].y};
                const uint32_t aa1[4] = {av0[mt].z, av1[mt].z, av0[mt].w, av1[mt].w};
#pragma unroll
                for (int nt = 0; nt < 4; nt++) {
                    const uint32_t bb0[2] = {bv[nt].x, bv[nt].y};
                    const uint32_t bb1[2] = {bv[nt].z, bv[nt].w};
                    mma_tf32(acc[mt][nt], aa0, bb0);
                    mma_tf32(acc[mt][nt], aa1, bb1);
                }
            }
        }
    }

    // --- epilogue ---
#pragma unroll
    for (int mt = 0; mt < 4; mt++) {
#pragma unroll
        for (int half = 0; half < 2; half++) {
            const int row = brow + m_base + mt * 16 + gID + half * 8;
            float* crow = C + (size_t)row * N;
            const float* rrow = (mode == 1) ? (R + (size_t)row * N) : nullptr;
#pragma unroll
            for (int nt = 0; nt < 4; nt++) {
                const int col = bcol + n_base + nt * 8 + tIG * 2;
                float v0 = acc[mt][nt][half * 2 + 0];
                float v1 = acc[mt][nt][half * 2 + 1];
                const float2 bb = *(const float2*)(bias + col);
                v0 += bb.x; v1 += bb.y;
                if (mode == 1) {
                    const float2 rr = *(const float2*)(rrow + col);
                    v0 += rr.x; v1 += rr.y;
                    *(float2*)(crow + col) = make_float2(v0, v1);
                } else if (mode == 2) {
                    v0 = 0.5f * v0 * (1.f + erff(v0 * 0.70710678118654752f));
                    v1 = 0.5f * v1 * (1.f + erff(v1 * 0.70710678118654752f));
                    crow[pj(col)]     = tf32r(v0);
                    crow[pj(col + 1)] = tf32r(v1);
                } else { // mode 3: QKV layout
                    if (col < 2 * H_) {
                        crow[pj(col)]     = tf32r(v0);
                        crow[pj(col + 1)] = tf32r(v1);
                    } else {
                        crow[col]     = tf32r(v0);
                        crow[col + 1] = tf32r(v1);
                    }
                }
            }
        }
    }
}

// ---------------------------------------------------------------------------
// LayerNorm: one block per row of 1024; output tf32-rounded + k-permuted
// ---------------------------------------------------------------------------
__global__ __launch_bounds__(256) void ln_kernel(
    const float* __restrict__ x, const float* __restrict__ w,
    const float* __restrict__ b, float* __restrict__ out)
{
    const int row = blockIdx.x;
    const int tid = threadIdx.x;
    const float* xr = x + (size_t)row * H_;

    float v[4];
    float s = 0.f, s2 = 0.f;
#pragma unroll
    for (int i = 0; i < 4; i++) {
        v[i] = xr[tid + 256 * i];
        s += v[i];
        s2 += v[i] * v[i];
    }
#pragma unroll
    for (int off = 16; off > 0; off >>= 1) {
        s  += __shfl_xor_sync(0xffffffffu, s,  off);
        s2 += __shfl_xor_sync(0xffffffffu, s2, off);
    }
    __shared__ float red[8], red2[8];
    const int wid = tid >> 5, lane = tid & 31;
    if (lane == 0) { red[wid] = s; red2[wid] = s2; }
    __syncthreads();
    if (tid < 32) {
        float a = (tid < 8) ? red[tid]  : 0.f;
        float c = (tid < 8) ? red2[tid] : 0.f;
#pragma unroll
        for (int off = 4; off > 0; off >>= 1) {
            a += __shfl_xor_sync(0xffffffffu, a, off);
            c += __shfl_xor_sync(0xffffffffu, c, off);
        }
        if (tid == 0) { red[0] = a; red2[0] = c; }
    }
    __syncthreads();
    const float mu  = red[0] * (1.f / H_);
    const float var = red2[0] * (1.f / H_) - mu * mu;
    const float rstd = rsqrtf(var + 1e-5f);

    float* orow = out + (size_t)row * H_;
#pragma unroll
    for (int i = 0; i < 4; i++) {
        const int c = tid + 256 * i;
        orow[pj(c)] = tf32r((v[i] - mu) * rstd * w[c] + b[c]);
    }
}

// ---------------------------------------------------------------------------
// Tensor-core flash attention (round-7 version).
// ---------------------------------------------------------------------------
#define QSTR 80
#define PSTR 68
#define ATTN_SMEM ((3 * 64 * QSTR + 64 * PSTR) * 4)

__global__ __launch_bounds__(128) void attn_mma(
    const float* __restrict__ qkv, float* __restrict__ O)
{
    extern __shared__ float sm[];
    float* Qs = sm;                    // [64][QSTR] (d permuted)
    float* Ks = Qs + 64 * QSTR;        // [64][QSTR] (d permuted)
    float* VT = Ks + 64 * QSTR;        // [d=64][QSTR] (kv permuted)
    float* Ps = VT + 64 * QSTR;        // [q=64][PSTR] (kv permuted)

    const int qt = blockIdx.x, bh = blockIdx.y;
    const int b = bh >> 4, h = bh & 15;
    const int tid = threadIdx.x, wid = tid >> 5, lane = tid & 31;
    const int gID = lane >> 2, tIG = lane & 3;
    const size_t row_base = (size_t)b * S_;
    const int qoff = h * HD_, koff = H_ + h * HD_, voff = 2 * H_ + h * HD_;

    {
        const int r = tid >> 1, ch = (tid & 1) * 32;
        const float4* src = (const float4*)(qkv + (row_base + qt * 64 + r) * QKV_N + qoff + ch);
        float4* dst = (float4*)(Qs + r * QSTR + ch);
#pragma unroll
        for (int j = 0; j < 8; j++) dst[j] = src[j];
    }
    __syncthreads();

    uint4 qa[4], qb[4];
    const int qrow = wid * 16 + gID;
#pragma unroll
    for (int kb = 0; kb < 4; kb++) {
        qa[kb] = *(const uint4*)(Qs + qrow * QSTR + kb * 16 + tIG * 4);
        qb[kb] = *(const uint4*)(Qs + (qrow + 8) * QSTR + kb * 16 + tIG * 4);
    }

    float m0 = -1e30f, m1 = -1e30f, l0 = 0.f, l1 = 0.f;
    float oacc[8][4];
#pragma unroll
    for (int i = 0; i < 8; i++)
#pragma unroll
        for (int j = 0; j < 4; j++) oacc[i][j] = 0.f;

    const float scale = 0.125f;

    for (int kt = 0; kt < S_ / 64; kt++) {
        __syncthreads();

        {
            const int r = tid >> 1, ch = (tid & 1) * 32;
            const float* gk = qkv + (row_base + kt * 64 + r) * QKV_N + koff + ch;
            const uint32_t sk = smem_u32(Ks + r * QSTR + ch);
#pragma unroll
            for (int j = 0; j < 8; j++) CP_ASYNC16(sk + j * 16, gk + j * 4);
            CP_COMMIT();
        }
        {
            const int kv = tid & 63, half = tid >> 6;
            const float4* gv = (const float4*)(qkv + (row_base + kt * 64 + kv) * QKV_N + voff + half * 32);
            const int pk = pj(kv);
#pragma unroll
            for (int j = 0; j < 8; j++) {
                const float4 v = gv[j];
                const int d = half * 32 + j * 4;
                VT[(d + 0) * QSTR + pk] = v.x;
                VT[(d + 1) * QSTR + pk] = v.y;
                VT[(d + 2) * QSTR + pk] = v.z;
                VT[(d + 3) * QSTR + pk] = v.w;
            }
        }
        asm volatile("cp.async.wait_group 0;" ::: "memory");
        __syncthreads();

        float sacc[8][4];
#pragma unroll
        for (int i = 0; i < 8; i++)
#pragma unroll
            for (int j = 0; j < 4; j++) sacc[i][j] = 0.f;

#pragma unroll
        for (int kb = 0; kb < 4; kb++) {
            const uint32_t aa0[4] = {qa[kb].x, qb[kb].x, qa[kb].y, qb[kb].y};
            const uint32_t aa1[4] = {qa[kb].z, qb[kb].z, qa[kb].w, qb[kb].w};
#pragma unroll
            for (int nt = 0; nt < 8; nt++) {
                const uint4 kv8 = *(const uint4*)(Ks + (nt * 8 + gID) * QSTR + kb * 16 + tIG * 4);
                const uint32_t bb0[2] = {kv8.x, kv8.y};
                const uint32_t bb1[2] = {kv8.z, kv8.w};
                mma_tf32(sacc[nt], aa0, bb0);
                mma_tf32(sacc[nt], aa1, bb1);
            }
        }

        float mx0 = -1e30f, mx1 = -1e30f;
#pragma unroll
        for (int nt = 0; nt < 8; nt++) {
            mx0 = fmaxf(mx0, fmaxf(sacc[nt][0], sacc[nt][1]));
            mx1 = fmaxf(mx1, fmaxf(sacc[nt][2], sacc[nt][3]));
        }
        mx0 = fmaxf(mx0, __shfl_xor_sync(0xffffffffu, mx0, 1));
        mx0 = fmaxf(mx0, __shfl_xor_sync(0xffffffffu, mx0, 2));
        mx1 = fmaxf(mx1, __shfl_xor_sync(0xffffffffu, mx1, 1));
        mx1 = fmaxf(mx1, __shfl_xor_sync(0xffffffffu, mx1, 2));

        const float mn0 = fmaxf(m0, mx0 * scale);
        const float mn1 = fmaxf(m1, mx1 * scale);
        const float corr0 = __expf(m0 - mn0);
        const float corr1 = __expf(m1 - mn1);

        float sum0 = 0.f, sum1 = 0.f;
#pragma unroll
        for (int nt = 0; nt < 8; nt++) {
            float p0 = tf32r(__expf(sacc[nt][0] * scale - mn0));
            float p1 = tf32r(__expf(sacc[nt][1] * scale - mn0));
            float p2 = tf32r(__expf(sacc[nt][2] * scale - mn1));
            float p3 = tf32r(__expf(sacc[nt][3] * scale - mn1));
            sum0 += p0 + p1; sum1 += p2 + p3;
            sacc[nt][0] = p0; sacc[nt][1] = p1; sacc[nt][2] = p2; sacc[nt][3] = p3;
        }
        sum0 += __shfl_xor_sync(0xffffffffu, sum0, 1);
        sum0 += __shfl_xor_sync(0xffffffffu, sum0, 2);
        sum1 += __shfl_xor_sync(0xffffffffu, sum1, 1);
        sum1 += __shfl_xor_sync(0xffffffffu, sum1, 2);

        l0 = l0 * corr0 + sum0; m0 = mn0;
        l1 = l1 * corr1 + sum1; m1 = mn1;
#pragma unroll
        for (int nt = 0; nt < 8; nt++) {
            oacc[nt][0] *= corr0; oacc[nt][1] *= corr0;
            oacc[nt][2] *= corr1; oacc[nt][3] *= corr1;
        }

#pragma unroll
        for (int nt = 0; nt < 8; nt++) {
            const int c = nt * 8 + tIG * 2;
            const int pc0 = pj(c), pc1 = pj(c + 1);
            Ps[qrow * PSTR + pc0]       = sacc[nt][0];
            Ps[qrow * PSTR + pc1]       = sacc[nt][1];
            Ps[(qrow + 8) * PSTR + pc0] = sacc[nt][2];
            Ps[(qrow + 8) * PSTR + pc1] = sacc[nt][3];
        }
        __syncwarp();

#pragma unroll
        for (int kb = 0; kb < 4; kb++) {
            const uint4 pa = *(const uint4*)(Ps + qrow * PSTR + kb * 16 + tIG * 4);
            const uint4 pb = *(const uint4*)(Ps + (qrow + 8) * PSTR + kb * 16 + tIG * 4);
            const uint32_t aa0[4] = {pa.x, pb.x, pa.y, pb.y};
            const uint32_t aa1[4] = {pa.z, pb.z, pa.w, pb.w};
#pragma unroll
            for (int nt = 0; nt < 8; nt++) {
                const uint4 vv = *(const uint4*)(VT + (nt * 8 + gID) * QSTR + kb * 16 + tIG * 4);
                const uint32_t bb0[2] = {vv.x, vv.y};
                const uint32_t bb1[2] = {vv.z, vv.w};
                mma_tf32(oacc[nt], aa0, bb0);
                mma_tf32(oacc[nt], aa1, bb1);
            }
        }
    }

    const float il0 = 1.f / l0, il1 = 1.f / l1;
    float* orow0 = O + (row_base + qt * 64 + qrow) * H_;
    float* orow1 = O + (row_base + qt * 64 + qrow + 8) * H_;
#pragma unroll
    for (int nt = 0; nt < 8; nt++) {
        const int c = h * HD_ + nt * 8 + tIG * 2;
        const int pc0 = pj(c), pc1 = pj(c + 1);
        orow0[pc0] = tf32r(oacc[nt][0] * il0);
        orow0[pc1] = tf32r(oacc[nt][1] * il0);
        orow1[pc0] = tf32r(oacc[nt][2] * il1);
        orow1[pc1] = tf32r(oacc[nt][3] * il1);
    }
}

// ---------------------------------------------------------------------------
// Launch
// ---------------------------------------------------------------------------
extern "C" void kernel_launch(void* const* d_in, const int* in_sizes, int n_in,
                              void* d_out, int out_size)
{
    const float* x     = (const float*)d_in[0];
    const float* ln1_w = (const float*)d_in[1];
    const float* ln1_b = (const float*)d_in[2];
    const float* Wqkv  = (const float*)d_in[3];
    const float* bqkv  = (const float*)d_in[4];
    const float* Wo    = (const float*)d_in[5];
    const float* bo    = (const float*)d_in[6];
    const float* ln2_w = (const float*)d_in[7];
    const float* ln2_b = (const float*)d_in[8];
    const float* fc1_w = (const float*)d_in[9];
    const float* fc1_b = (const float*)d_in[10];
    const float* fc2_w = (const float*)d_in[11];
    const float* fc2_b = (const float*)d_in[12];
    float* out = (float*)d_out;

    float *h, *qkv, *o, *x2, *h2, *a, *wqkvT, *woT, *w1T, *w2T;
    cudaGetSymbolAddress((void**)&h,   g_h);
    cudaGetSymbolAddress((void**)&qkv, g_qkv);
    cudaGetSymbolAddress((void**)&o,   g_o);
    cudaGetSymbolAddress((void**)&x2,  g_x2);
    cudaGetSymbolAddress((void**)&h2,  g_h2);
    cudaGetSymbolAddress((void**)&a,   g_a);
    cudaGetSymbolAddress((void**)&wqkvT, g_wqkvT);
    cudaGetSymbolAddress((void**)&woT,   g_woT);
    cudaGetSymbolAddress((void**)&w1T,   g_w1T);
    cudaGetSymbolAddress((void**)&w2T,   g_w2T);

    cudaFuncSetAttribute(attn_mma,
                         cudaFuncAttributeMaxDynamicSharedMemorySize, ATTN_SMEM);
    cudaFuncSetAttribute(gemm_mma,
                         cudaFuncAttributeMaxDynamicSharedMemorySize, GEMM_SMEM);

    // 0) weight prepass: transpose + tf32-round + k-permute
    wtrans<<<dim3(QKV_N / 32, H_ / 32), 256>>>(Wqkv, wqkvT, H_, QKV_N);
    wtrans<<<dim3(H_ / 32,    H_ / 32), 256>>>(Wo,   woT,   H_, H_);
    wtrans<<<dim3(E_ / 32,    H_ / 32), 256>>>(fc1_w, w1T,  H_, E_);
    wtrans<<<dim3(H_ / 32,    E_ / 32), 256>>>(fc2_w, w2T,  E_, H_);

    // 1) LN1 (perm+tf32 out)
    ln_kernel<<<M_, 256>>>(x, ln1_w, ln1_b, h);
    // 2) QKV projection (mode 3: Q,K perm+tf32; V plain tf32)
    gemm_mma<<<dim3(QKV_N / 128, M_ / 128), 256, GEMM_SMEM>>>(
        h, wqkvT, bqkv, nullptr, qkv, M_, QKV_N, H_, 3);
    // 3) attention (tensor cores; perm+tf32 out)
    attn_mma<<<dim3(S_ / 64, B_ * NH_), 128, ATTN_SMEM>>>(qkv, o);
    // 4) Wo + residual
    gemm_mma<<<dim3(H_ / 128, M_ / 128), 256, GEMM_SMEM>>>(
        o, woT, bo, x, x2, M_, H_, H_, 1);
    // 5) LN2 (perm+tf32 out)
    ln_kernel<<<M_, 256>>>(x2, ln2_w, ln2_b, h2);
    // 6) FC1 + GELU (perm+tf32 out)
    gemm_mma<<<dim3(E_ / 128, M_ / 128), 256, GEMM_SMEM>>>(
        h2, w1T, fc1_b, nullptr, a, M_, E_, H_, 2);
    // 7) FC2 + residual -> out
    gemm_mma<<<dim3(H_ / 128, M_ / 128), 256, GEMM_SMEM>>>(
        a, w2T, fc2_b, x2, out, M_, H_, E_, 1);
}